// round 4
// baseline (speedup 1.0000x reference)
#include <cuda_runtime.h>
#include <cuda_fp16.h>
#include <cstdint>

#define NN    6000
#define FIN   300
#define HIDD  128
#define NH    8
#define ALPHAK 0.2f
#define MAXNNZ 4000000
#define SCAN_CH 6          // ceil(6000/1024)
#define NW 188             // ceil(6000/32)
#define NCH 94             // source chunks of 64 (94*64 = 6016)
#define NT  47             // dest tiles of 128 (47*128 = 6016)
#define KSPL 8             // layer-2 split over chunks

// ---------------- device scratch ----------------
__device__ __align__(256) __half g_Wh16[NN * NH * HIDD];   // [n][h][c]
__device__ __align__(256) __half g_x16[NN * 304];          // fp16 x, K padded to 304
__device__ float    g_f1c[NN * NH];
__device__ float    g_f2c[NN * NH];
__device__ float    g_rmax1[NN * NH];
__device__ __align__(256) __half g_hcat16[NN * NH * HIDD];
__device__ float    g_Wh2part[4 * NN * HIDD];
__device__ __align__(256) __half g_Wh2h[NN * HIDD];
__device__ float    g_g1[NN];
__device__ float    g_g2[NN];
__device__ float    g_rmax2[NN];
__device__ float    g_att2part[KSPL * 6016 * HIDD];        // 24.7 MB
__device__ float    g_s2part[KSPL * 6016];
__device__ int      g_rowptr[NN + 1];
__device__ int      g_rp2[NN * (NCH + 1)];
__device__ unsigned g_bits[NN * NW];
__device__ int      g_cols[MAXNNZ];

// ---------------- CSR build ----------------
__global__ __launch_bounds__(128) void count_kernel(const float* __restrict__ adj) {
    int row  = blockIdx.x * 4 + (threadIdx.x >> 5);
    int lane = threadIdx.x & 31;
    if (row >= NN) return;
    const float* arow = adj + (size_t)row * NN;
    int cnt = 0;
    for (int w0 = 0; w0 < NW; w0++) {
        int col = w0 * 32 + lane;
        float v = (col < NN) ? arow[col] : 0.f;
        unsigned b = __ballot_sync(0xffffffffu, v > 0.f);
        if (lane == 0) {
            g_bits[row * NW + w0] = b;
            cnt += __popc(b);
        }
    }
    if (lane == 0) g_rowptr[row + 1] = cnt;
}

__global__ __launch_bounds__(1024) void scan_kernel() {
    __shared__ int part[1024];
    int t = threadIdx.x;
    int base = t * SCAN_CH;
    int loc[SCAN_CH];
    int s = 0;
    #pragma unroll
    for (int i = 0; i < SCAN_CH; i++) {
        int idx = base + i;
        int v = (idx < NN) ? g_rowptr[idx + 1] : 0;
        s += v;
        loc[i] = s;
    }
    part[t] = s;
    __syncthreads();
    for (int off = 1; off < 1024; off <<= 1) {
        int v = 0;
        if (t >= off) v = part[t - off];
        __syncthreads();
        if (t >= off) part[t] += v;
        __syncthreads();
    }
    int excl = (t == 0) ? 0 : part[t - 1];
    #pragma unroll
    for (int i = 0; i < SCAN_CH; i++) {
        int idx = base + i;
        if (idx < NN) g_rowptr[idx + 1] = excl + loc[i];
    }
    if (t == 0) g_rowptr[0] = 0;
}

__global__ __launch_bounds__(128) void fill_kernel() {
    int row  = blockIdx.x * 4 + (threadIdx.x >> 5);
    int lane = threadIdx.x & 31;
    if (row >= NN) return;
    int base = g_rowptr[row];
    for (int w0 = 0; w0 < NW; w0++) {
        unsigned bits = g_bits[row * NW + w0];
        if (bits) {
            if ((bits >> lane) & 1u) {
                int pos = base + __popc(bits & ((1u << lane) - 1u));
                g_cols[pos] = w0 * 32 + lane;
            }
            base += __popc(bits);
        }
    }
}

// per-(row, chunk) CSR segment starts via binary search
__global__ __launch_bounds__(128) void rp2_kernel() {
    int n = blockIdx.x;
    int t = threadIdx.x;
    if (t > NCH) return;
    int lo = g_rowptr[n], hi = g_rowptr[n + 1];
    int target = t * 64;
    while (lo < hi) {
        int mid = (lo + hi) >> 1;
        if (g_cols[mid] < target) lo = mid + 1; else hi = mid;
    }
    g_rp2[n * (NCH + 1) + t] = lo;
}

// ---------------- x -> fp16 padded ----------------
__global__ __launch_bounds__(256) void x16_kernel(const float* __restrict__ x) {
    int i = blockIdx.x * 256 + threadIdx.x;
    if (i >= NN * 304) return;
    int n = i / 304, c = i - n * 304;
    g_x16[i] = (c < FIN) ? __float2half_rn(x[(size_t)n * FIN + c]) : __ushort_as_half(0);
}

// ---------------- tensor-core fp16 GEMM ----------------
__device__ __forceinline__ void mma16816(float* c, const uint32_t* a, const uint32_t* b) {
    asm volatile(
        "mma.sync.aligned.m16n8k16.row.col.f32.f16.f16.f32 "
        "{%0,%1,%2,%3}, {%4,%5,%6,%7}, {%8,%9}, {%0,%1,%2,%3};\n"
        : "+f"(c[0]), "+f"(c[1]), "+f"(c[2]), "+f"(c[3])
        : "r"(a[0]), "r"(a[1]), "r"(a[2]), "r"(a[3]), "r"(b[0]), "r"(b[1]));
}

// MODE 0: g_Wh16[m][h*128+c] = x16[m,304] @ W_heads[h][300,128], grid (47, 8)
// MODE 1: g_Wh2part[s] = hcat16[:, s*256:(s+1)*256] @ W_out[s*256:,:], grid (47, 4)
template <int MODE>
__global__ __launch_bounds__(256) void hgemm(const float* __restrict__ Bf) {
    constexpr int KTOT = (MODE == 0) ? 304 : 256;
    constexpr int NIT  = KTOT / 16;
    constexpr int KVAL = (MODE == 0) ? FIN : 256;  // valid K rows in B
    __shared__ __half As[128][18];
    __shared__ __half Bs[128][18];

    int tid  = threadIdx.x;
    int lane = tid & 31;
    int wid  = tid >> 5;
    int wm = wid & 3, wn = wid >> 2;
    int m0 = blockIdx.x * 128;
    int sl = blockIdx.y;
    const float*  Bg = Bf + (size_t)sl * ((MODE == 0) ? FIN * HIDD : 256 * HIDD);
    const __half* Ag = (MODE == 0) ? g_x16 : (g_hcat16 + sl * 256);
    const int lda = (MODE == 0) ? 304 : 1024;

    float acc[2][8][4];
    #pragma unroll
    for (int i = 0; i < 2; i++)
        #pragma unroll
        for (int j = 0; j < 8; j++)
            #pragma unroll
            for (int q = 0; q < 4; q++) acc[i][j][q] = 0.f;

    uint4  ph;
    float4 pb0, pb1;
    const float4 Z4 = make_float4(0.f, 0.f, 0.f, 0.f);

    auto loadG = [&](int it) {
        int k0 = it * 16;
        int r = tid >> 1, hoff = (tid & 1) * 8;
        int gr = m0 + r;
        ph = (gr < NN) ? *(const uint4*)(Ag + (size_t)gr * lda + k0 + hoff)
                       : make_uint4(0u, 0u, 0u, 0u);
        int kr = tid >> 4, c0 = (tid & 15) * 8;
        bool kok = (k0 + kr) < KVAL;
        pb0 = kok ? *(const float4*)(Bg + (size_t)(k0 + kr) * HIDD + c0)     : Z4;
        pb1 = kok ? *(const float4*)(Bg + (size_t)(k0 + kr) * HIDD + c0 + 4) : Z4;
    };

    auto stS = [&]() {
        int r = tid >> 1, hoff = (tid & 1) * 8;
        *(uint32_t*)&As[r][hoff]     = ph.x;
        *(uint32_t*)&As[r][hoff + 2] = ph.y;
        *(uint32_t*)&As[r][hoff + 4] = ph.z;
        *(uint32_t*)&As[r][hoff + 6] = ph.w;
        int kr = tid >> 4, c0 = (tid & 15) * 8;
        Bs[c0 + 0][kr] = __float2half_rn(pb0.x);
        Bs[c0 + 1][kr] = __float2half_rn(pb0.y);
        Bs[c0 + 2][kr] = __float2half_rn(pb0.z);
        Bs[c0 + 3][kr] = __float2half_rn(pb0.w);
        Bs[c0 + 4][kr] = __float2half_rn(pb1.x);
        Bs[c0 + 5][kr] = __float2half_rn(pb1.y);
        Bs[c0 + 6][kr] = __float2half_rn(pb1.z);
        Bs[c0 + 7][kr] = __float2half_rn(pb1.w);
    };

    loadG(0);
    int r = lane >> 2, c2 = (lane & 3) * 2;
    for (int it = 0; it < NIT; it++) {
        stS();
        __syncthreads();
        if (it + 1 < NIT) loadG(it + 1);

        uint32_t afr[2][4], bfr[8][2];
        #pragma unroll
        for (int mi = 0; mi < 2; mi++) {
            int row = wm * 32 + mi * 16 + r;
            afr[mi][0] = *(const uint32_t*)&As[row][c2];
            afr[mi][1] = *(const uint32_t*)&As[row + 8][c2];
            afr[mi][2] = *(const uint32_t*)&As[row][c2 + 8];
            afr[mi][3] = *(const uint32_t*)&As[row + 8][c2 + 8];
        }
        #pragma unroll
        for (int ni = 0; ni < 8; ni++) {
            int col = wn * 64 + ni * 8 + r;
            bfr[ni][0] = *(const uint32_t*)&Bs[col][c2];
            bfr[ni][1] = *(const uint32_t*)&Bs[col][c2 + 8];
        }
        #pragma unroll
        for (int mi = 0; mi < 2; mi++)
            #pragma unroll
            for (int ni = 0; ni < 8; ni++)
                mma16816(acc[mi][ni], afr[mi], bfr[ni]);
        __syncthreads();
    }

    #pragma unroll
    for (int mi = 0; mi < 2; mi++)
        #pragma unroll
        for (int hh = 0; hh < 2; hh++) {
            int row = m0 + wm * 32 + mi * 16 + r + hh * 8;
            if (row < NN) {
                #pragma unroll
                for (int ni = 0; ni < 8; ni++) {
                    int col = wn * 64 + ni * 8 + c2;
                    if (MODE == 0) {
                        *(__half2*)(g_Wh16 + (size_t)row * 1024 + sl * 128 + col) =
                            __float22half2_rn(make_float2(acc[mi][ni][hh * 2], acc[mi][ni][hh * 2 + 1]));
                    } else {
                        *(float2*)(g_Wh2part + (size_t)sl * NN * HIDD + (size_t)row * HIDD + col) =
                            make_float2(acc[mi][ni][hh * 2], acc[mi][ni][hh * 2 + 1]);
                    }
                }
            }
        }
}

// ---------------- f1/f2 ----------------
__global__ __launch_bounds__(128) void f12_kernel(const float* __restrict__ a_heads) {
    int gw   = blockIdx.x * 4 + (threadIdx.x >> 5);   // gw = n*8 + h
    int lane = threadIdx.x & 31;
    if (gw >= NN * NH) return;
    int h = gw & 7;
    const __half2* wh = (const __half2*)(g_Wh16 + (size_t)gw * HIDD);
    const float* a1 = a_heads + h * 2 * HIDD;
    float s1 = 0.f, s2 = 0.f;
    #pragma unroll
    for (int i = 0; i < 2; i++) {
        int o2 = lane + i * 32;
        float2 w = __half22float2(wh[o2]);
        s1 += w.x * a1[2 * o2] + w.y * a1[2 * o2 + 1];
        s2 += w.x * a1[HIDD + 2 * o2] + w.y * a1[HIDD + 2 * o2 + 1];
    }
    #pragma unroll
    for (int off = 16; off; off >>= 1) {
        s1 += __shfl_down_sync(0xffffffffu, s1, off);
        s2 += __shfl_down_sync(0xffffffffu, s2, off);
    }
    if (lane == 0) { g_f1c[gw] = s1; g_f2c[gw] = s2; }
}

// ---------------- exact per-row score max ----------------
__global__ __launch_bounds__(256) void rowmax1_kernel() {
    int n = blockIdx.x;
    int w = threadIdx.x >> 5, lane = threadIdx.x & 31;
    int beg = g_rowptr[n], end = g_rowptr[n + 1];
    float f1n = g_f1c[n * 8 + w];
    float m = -3.0e38f;
    for (int j = beg + lane; j < end; j += 32) {
        int col = g_cols[j];
        float v = f1n + g_f2c[col * 8 + w];
        v = (v > 0.f) ? v : ALPHAK * v;
        m = fmaxf(m, v);
    }
    #pragma unroll
    for (int o = 16; o; o >>= 1) m = fmaxf(m, __shfl_xor_sync(0xffffffffu, m, o));
    if (lane == 0) g_rmax1[n * 8 + w] = m;
}

__global__ __launch_bounds__(256) void rowmax2_kernel() {
    int n = blockIdx.x * 8 + (threadIdx.x >> 5);
    int lane = threadIdx.x & 31;
    if (n >= NN) return;
    int beg = g_rowptr[n], end = g_rowptr[n + 1];
    float g1n = g_g1[n];
    float m = -3.0e38f;
    for (int j = beg + lane; j < end; j += 32) {
        float v = g1n + g_g2[g_cols[j]];
        v = (v > 0.f) ? v : ALPHAK * v;
        m = fmaxf(m, v);
    }
    #pragma unroll
    for (int o = 16; o; o >>= 1) m = fmaxf(m, __shfl_xor_sync(0xffffffffu, m, o));
    if (lane == 0) g_rmax2[n] = m;
}

// ---------------- block-dense attention aggregation via HMMA ----------------
// LAYER 0: grid (47, 8) = (dest tile, head). Out: g_hcat16 with ELU.
// LAYER 1: grid (47, 8) = (dest tile, chunk-split ks). Out: fp32 partials.
template <int LAYER>
__global__ __launch_bounds__(256, 2) void attn_mma(void) {
    constexpr int PLD = 72;    // P row stride (halves)
    constexpr int WLD = 136;   // Ws row stride (halves)
    __shared__ __half P[128 * PLD];
    __shared__ __half Ws[64 * WLD];
    __shared__ float srow[128];

    int tile = blockIdx.x;
    int n0 = tile * 128;
    int tid = threadIdx.x, lane = tid & 31, wid = tid >> 5;
    int wm = wid & 3, wn = wid >> 2;       // 4 (m) x 2 (n)
    int r = lane >> 2, c2 = (lane & 3) * 2;

    int h, ch0, ch1;
    if (LAYER == 0) { h = blockIdx.y; ch0 = 0; ch1 = NCH; }
    else            { h = 0; ch0 = blockIdx.y * 12; ch1 = min(NCH, ch0 + 12); }

    // fill assignment: 2 threads per dest row
    int fr = tid >> 1, half = tid & 1;
    int grow = n0 + fr;
    bool rowok = grow < NN;
    int grc = rowok ? grow : 0;
    float f1n, rmax;
    if (LAYER == 0) { f1n = g_f1c[grc * 8 + h]; rmax = g_rmax1[grc * 8 + h]; }
    else            { f1n = g_g1[grc];          rmax = g_rmax2[grc]; }
    const int* rp2 = g_rp2 + (size_t)grc * (NCH + 1);

    const __half* Wg = (LAYER == 0) ? (g_Wh16 + h * 128) : g_Wh2h;
    const int wstride = (LAYER == 0) ? 1024 : 128;

    float acc[2][8][4];
    #pragma unroll
    for (int i = 0; i < 2; i++)
        #pragma unroll
        for (int j = 0; j < 8; j++)
            #pragma unroll
            for (int q = 0; q < 4; q++) acc[i][j][q] = 0.f;
    float s = 0.f;

    for (int ch = ch0; ch < ch1; ch++) {
        int c0 = ch * 64;
        __syncthreads();   // prior MMA finished with P/Ws
        // zero P (128*72 halves = 18432 B)
        {
            uint2* Pw = (uint2*)P;
            #pragma unroll
            for (int i = 0; i < 9; i++) Pw[tid + i * 256] = make_uint2(0u, 0u);
        }
        // load Ws chunk [64][128] (uint4 = 8 halves, 4 per thread)
        {
            #pragma unroll
            for (int i = 0; i < 4; i++) {
                int idx = tid + i * 256;
                int row = idx >> 4, cq = (idx & 15) * 8;
                int src = c0 + row;
                uint4 v = (src < NN) ? *(const uint4*)(Wg + (size_t)src * wstride + cq)
                                     : make_uint4(0u, 0u, 0u, 0u);
                *(uint4*)&Ws[row * WLD + cq] = v;
            }
        }
        // scatter sparse attention weights into P
        if (rowok) {
            int s0 = rp2[ch], s1 = rp2[ch + 1];
            for (int j = s0 + half; j < s1; j += 2) {
                int col = g_cols[j];
                float f2v = (LAYER == 0) ? g_f2c[col * 8 + h] : g_g2[col];
                float v = f1n + f2v;
                v = (v > 0.f) ? v : ALPHAK * v;
                float w = __expf(v - rmax);
                P[fr * PLD + (col - c0)] = __float2half_rn(w);
                s += w;
            }
        }
        __syncthreads();
        // MMA: acc += P[128x64] @ Ws[64x128]
        #pragma unroll
        for (int ks = 0; ks < 4; ks++) {
            int k0 = ks * 16;
            uint32_t afr[2][4];
            #pragma unroll
            for (int mi = 0; mi < 2; mi++) {
                const __half* pb = P + (wm * 32 + mi * 16 + r) * PLD + k0;
                afr[mi][0] = *(const uint32_t*)(pb + c2);
                afr[mi][1] = *(const uint32_t*)(pb + 8 * PLD + c2);
                afr[mi][2] = *(const uint32_t*)(pb + c2 + 8);
                afr[mi][3] = *(const uint32_t*)(pb + 8 * PLD + c2 + 8);
            }
            uint32_t bfr[8][2];
            #pragma unroll
            for (int q = 0; q < 4; q++) {
                int mat = lane >> 3, ri = lane & 7;
                int krow = k0 + ((mat & 1) ? 8 : 0) + ri;
                int cb = wn * 64 + q * 16 + ((mat >> 1) ? 8 : 0);
                uint32_t a = (uint32_t)__cvta_generic_to_shared(&Ws[krow * WLD + cb]);
                asm volatile(
                    "ldmatrix.sync.aligned.m8n8.x4.trans.shared.b16 {%0,%1,%2,%3}, [%4];"
                    : "=r"(bfr[2 * q][0]), "=r"(bfr[2 * q][1]),
                      "=r"(bfr[2 * q + 1][0]), "=r"(bfr[2 * q + 1][1])
                    : "r"(a));
            }
            #pragma unroll
            for (int mi = 0; mi < 2; mi++)
                #pragma unroll
                for (int ni = 0; ni < 8; ni++)
                    mma16816(acc[mi][ni], afr[mi], bfr[ni]);
        }
    }

    // rowsum: combine thread pair
    s += __shfl_xor_sync(0xffffffffu, s, 1);
    if (LAYER == 0) {
        if (half == 0) srow[fr] = (s > 0.f) ? s : 1.f;
        __syncthreads();
        #pragma unroll
        for (int mi = 0; mi < 2; mi++)
            #pragma unroll
            for (int hh = 0; hh < 2; hh++) {
                int rl = wm * 32 + mi * 16 + r + hh * 8;
                int row = n0 + rl;
                if (row < NN) {
                    float inv = 1.f / srow[rl];
                    #pragma unroll
                    for (int ni = 0; ni < 8; ni++) {
                        int col = wn * 64 + ni * 8 + c2;
                        float vx = acc[mi][ni][hh * 2] * inv;
                        float vy = acc[mi][ni][hh * 2 + 1] * inv;
                        vx = (vx > 0.f) ? vx : expm1f(vx);
                        vy = (vy > 0.f) ? vy : expm1f(vy);
                        *(__half2*)(g_hcat16 + (size_t)row * 1024 + h * 128 + col) =
                            __float22half2_rn(make_float2(vx, vy));
                    }
                }
            }
    } else {
        if (half == 0) g_s2part[blockIdx.y * 6016 + n0 + fr] = s;
        float* outp = g_att2part + (size_t)blockIdx.y * 6016 * HIDD;
        #pragma unroll
        for (int mi = 0; mi < 2; mi++)
            #pragma unroll
            for (int hh = 0; hh < 2; hh++) {
                int row = n0 + wm * 32 + mi * 16 + r + hh * 8;
                #pragma unroll
                for (int ni = 0; ni < 8; ni++) {
                    int col = wn * 64 + ni * 8 + c2;
                    *(float2*)(outp + (size_t)row * HIDD + col) =
                        make_float2(acc[mi][ni][hh * 2], acc[mi][ni][hh * 2 + 1]);
                }
            }
    }
}

// ---------------- split-K reduce (layer-2 GEMM) + g1/g2 + fp16 Wh2 ----------------
__global__ __launch_bounds__(128) void reduce_g12_kernel(const float* __restrict__ a_out) {
    int n = blockIdx.x, t = threadIdx.x;
    size_t idx = (size_t)n * HIDD + t;
    float w = g_Wh2part[idx]
            + g_Wh2part[(size_t)NN * HIDD + idx]
            + g_Wh2part[(size_t)2 * NN * HIDD + idx]
            + g_Wh2part[(size_t)3 * NN * HIDD + idx];
    g_Wh2h[idx] = __float2half_rn(w);
    __shared__ float r1[128], r2[128];
    r1[t] = w * a_out[t];
    r2[t] = w * a_out[HIDD + t];
    __syncthreads();
    for (int o = 64; o; o >>= 1) {
        if (t < o) { r1[t] += r1[t + o]; r2[t] += r2[t + o]; }
        __syncthreads();
    }
    if (t == 0) { g_g1[n] = r1[0]; g_g2[n] = r2[0]; }
}

// ---------------- combine layer-2 partials ----------------
__global__ __launch_bounds__(128) void reduce2_kernel(float* __restrict__ dout) {
    int n = blockIdx.x, t = threadIdx.x;
    float s = 0.f;
    #pragma unroll
    for (int k = 0; k < KSPL; k++) s += g_s2part[k * 6016 + n];
    float a = 0.f;
    #pragma unroll
    for (int k = 0; k < KSPL; k++)
        a += g_att2part[((size_t)k * 6016 + n) * HIDD + t];
    dout[(size_t)n * HIDD + t] = a / s;
}

// ---------------- launch ----------------
extern "C" void kernel_launch(void* const* d_in, const int* in_sizes, int n_in,
                              void* d_out, int out_size) {
    const float* x       = (const float*)d_in[0];
    const float* adj     = (const float*)d_in[1];
    const float* W_heads = (const float*)d_in[2];
    const float* a_heads = (const float*)d_in[3];
    const float* W_out   = (const float*)d_in[4];
    const float* a_out   = (const float*)d_in[5];
    float* out = (float*)d_out;

    count_kernel<<<1500, 128>>>(adj);
    scan_kernel<<<1, 1024>>>();
    fill_kernel<<<1500, 128>>>();
    rp2_kernel<<<NN, 128>>>();
    x16_kernel<<<(NN * 304 + 255) / 256, 256>>>(x);

    hgemm<0><<<dim3(NT, 8), 256>>>(W_heads);
    f12_kernel<<<(NN * NH + 3) / 4, 128>>>(a_heads);
    rowmax1_kernel<<<NN, 256>>>();

    attn_mma<0><<<dim3(NT, 8), 256>>>();

    hgemm<1><<<dim3(NT, 4), 256>>>(W_out);
    reduce_g12_kernel<<<NN, 128>>>(a_out);
    rowmax2_kernel<<<(NN + 7) / 8, 256>>>();

    attn_mma<1><<<dim3(NT, KSPL), 256>>>();
    reduce2_kernel<<<NN, 128>>>(out);
}

// round 5
// speedup vs baseline: 1.1958x; 1.1958x over previous
#include <cuda_runtime.h>
#include <cuda_fp16.h>
#include <cstdint>

#define NN    6000
#define FIN   300
#define HIDD  128
#define NH    8
#define ALPHAK 0.2f
#define EMAX  2200000      // nnz ≈ 1.81M deterministic; safe cap
#define SCAN_CH 6          // ceil(6000/1024)
#define NW 188             // ceil(6000/32)
#define NTIL 188           // ceil(6000/32) row tiles of 32
#define NWIN 12            // windows of 512 cols (12*512 = 6144)

// ---------------- device scratch ----------------
__device__ __align__(256) __half g_Wh16[NN * NH * HIDD];   // [n][h][c]
__device__ __align__(256) __half g_x16[NN * 304];          // fp16 x, K padded
__device__ float    g_f1c[NH * NN];                        // [h][n]
__device__ float    g_f2c[NH * NN];                        // [h][n]
__device__ float    g_sinv1[NH * NN];
__device__ float    g_sinv2[NN];
__device__ __align__(256) __half g_hcat16[NN * NH * HIDD];
__device__ float    g_Wh2part[4 * NN * HIDD];
__device__ __align__(256) __half g_Wh2h[NN * HIDD];
__device__ float    g_g1[NN];
__device__ float    g_g2[NN];
__device__ uint2    g_cw[(size_t)NH * EMAX];               // {fp32 w, col} per head
__device__ int      g_rowptr[NN + 1];
__device__ int      g_rpw[NN * (NWIN + 1)];
__device__ unsigned g_bits[NN * NW];
__device__ int      g_cols[EMAX];

// ---------------- CSR build ----------------
__global__ __launch_bounds__(128) void count_kernel(const float* __restrict__ adj) {
    int row  = blockIdx.x * 4 + (threadIdx.x >> 5);
    int lane = threadIdx.x & 31;
    if (row >= NN) return;
    const float* arow = adj + (size_t)row * NN;
    int cnt = 0;
    for (int w0 = 0; w0 < NW; w0++) {
        int col = w0 * 32 + lane;
        float v = (col < NN) ? arow[col] : 0.f;
        unsigned b = __ballot_sync(0xffffffffu, v > 0.f);
        if (lane == 0) {
            g_bits[row * NW + w0] = b;
            cnt += __popc(b);
        }
    }
    if (lane == 0) g_rowptr[row + 1] = cnt;
}

__global__ __launch_bounds__(1024) void scan_kernel() {
    __shared__ int part[1024];
    int t = threadIdx.x;
    int base = t * SCAN_CH;
    int loc[SCAN_CH];
    int s = 0;
    #pragma unroll
    for (int i = 0; i < SCAN_CH; i++) {
        int idx = base + i;
        int v = (idx < NN) ? g_rowptr[idx + 1] : 0;
        s += v;
        loc[i] = s;
    }
    part[t] = s;
    __syncthreads();
    for (int off = 1; off < 1024; off <<= 1) {
        int v = 0;
        if (t >= off) v = part[t - off];
        __syncthreads();
        if (t >= off) part[t] += v;
        __syncthreads();
    }
    int excl = (t == 0) ? 0 : part[t - 1];
    #pragma unroll
    for (int i = 0; i < SCAN_CH; i++) {
        int idx = base + i;
        if (idx < NN) g_rowptr[idx + 1] = excl + loc[i];
    }
    if (t == 0) g_rowptr[0] = 0;
}

__global__ __launch_bounds__(128) void fill_kernel() {
    int row  = blockIdx.x * 4 + (threadIdx.x >> 5);
    int lane = threadIdx.x & 31;
    if (row >= NN) return;
    int base = g_rowptr[row];
    for (int w0 = 0; w0 < NW; w0++) {
        unsigned bits = g_bits[row * NW + w0];
        if (bits) {
            if ((bits >> lane) & 1u) {
                int pos = base + __popc(bits & ((1u << lane) - 1u));
                g_cols[pos] = w0 * 32 + lane;
            }
            base += __popc(bits);
        }
    }
}

// per-(row, window-of-512) CSR segment starts
__global__ __launch_bounds__(64) void rpw_kernel() {
    int n = blockIdx.x;
    int t = threadIdx.x;
    if (t > NWIN) return;
    int lo = g_rowptr[n], hi = g_rowptr[n + 1];
    int target = t * 512;
    while (lo < hi) {
        int mid = (lo + hi) >> 1;
        if (g_cols[mid] < target) lo = mid + 1; else hi = mid;
    }
    g_rpw[n * (NWIN + 1) + t] = lo;
}

// ---------------- x -> fp16 padded ----------------
__global__ __launch_bounds__(256) void x16_kernel(const float* __restrict__ x) {
    int i = blockIdx.x * 256 + threadIdx.x;
    if (i >= NN * 304) return;
    int n = i / 304, c = i - n * 304;
    g_x16[i] = (c < FIN) ? __float2half_rn(x[(size_t)n * FIN + c]) : __ushort_as_half(0);
}

// ---------------- tensor-core fp16 GEMM ----------------
__device__ __forceinline__ void mma16816(float* c, const uint32_t* a, const uint32_t* b) {
    asm volatile(
        "mma.sync.aligned.m16n8k16.row.col.f32.f16.f16.f32 "
        "{%0,%1,%2,%3}, {%4,%5,%6,%7}, {%8,%9}, {%0,%1,%2,%3};\n"
        : "+f"(c[0]), "+f"(c[1]), "+f"(c[2]), "+f"(c[3])
        : "r"(a[0]), "r"(a[1]), "r"(a[2]), "r"(a[3]), "r"(b[0]), "r"(b[1]));
}

// MODE 0: g_Wh16[m][h*128+c] = x16 @ W_heads[h], grid (47, 8)
// MODE 1: g_Wh2part[s] = hcat16[:, s*256:(s+1)*256] @ W_out[s*256:,:], grid (47, 4)
template <int MODE>
__global__ __launch_bounds__(256) void hgemm(const float* __restrict__ Bf) {
    constexpr int KTOT = (MODE == 0) ? 304 : 256;
    constexpr int NIT  = KTOT / 16;
    constexpr int KVAL = (MODE == 0) ? FIN : 256;
    __shared__ __half As[128][18];
    __shared__ __half Bs[128][18];

    int tid  = threadIdx.x;
    int lane = tid & 31;
    int wid  = tid >> 5;
    int wm = wid & 3, wn = wid >> 2;
    int m0 = blockIdx.x * 128;
    int sl = blockIdx.y;
    const float*  Bg = Bf + (size_t)sl * ((MODE == 0) ? FIN * HIDD : 256 * HIDD);
    const __half* Ag = (MODE == 0) ? g_x16 : (g_hcat16 + sl * 256);
    const int lda = (MODE == 0) ? 304 : 1024;

    float acc[2][8][4];
    #pragma unroll
    for (int i = 0; i < 2; i++)
        #pragma unroll
        for (int j = 0; j < 8; j++)
            #pragma unroll
            for (int q = 0; q < 4; q++) acc[i][j][q] = 0.f;

    uint4  ph;
    float4 pb0, pb1;
    const float4 Z4 = make_float4(0.f, 0.f, 0.f, 0.f);

    auto loadG = [&](int it) {
        int k0 = it * 16;
        int r = tid >> 1, hoff = (tid & 1) * 8;
        int gr = m0 + r;
        ph = (gr < NN) ? *(const uint4*)(Ag + (size_t)gr * lda + k0 + hoff)
                       : make_uint4(0u, 0u, 0u, 0u);
        int kr = tid >> 4, c0 = (tid & 15) * 8;
        bool kok = (k0 + kr) < KVAL;
        pb0 = kok ? *(const float4*)(Bg + (size_t)(k0 + kr) * HIDD + c0)     : Z4;
        pb1 = kok ? *(const float4*)(Bg + (size_t)(k0 + kr) * HIDD + c0 + 4) : Z4;
    };

    auto stS = [&]() {
        int r = tid >> 1, hoff = (tid & 1) * 8;
        *(uint32_t*)&As[r][hoff]     = ph.x;
        *(uint32_t*)&As[r][hoff + 2] = ph.y;
        *(uint32_t*)&As[r][hoff + 4] = ph.z;
        *(uint32_t*)&As[r][hoff + 6] = ph.w;
        int kr = tid >> 4, c0 = (tid & 15) * 8;
        Bs[c0 + 0][kr] = __float2half_rn(pb0.x);
        Bs[c0 + 1][kr] = __float2half_rn(pb0.y);
        Bs[c0 + 2][kr] = __float2half_rn(pb0.z);
        Bs[c0 + 3][kr] = __float2half_rn(pb0.w);
        Bs[c0 + 4][kr] = __float2half_rn(pb1.x);
        Bs[c0 + 5][kr] = __float2half_rn(pb1.y);
        Bs[c0 + 6][kr] = __float2half_rn(pb1.z);
        Bs[c0 + 7][kr] = __float2half_rn(pb1.w);
    };

    loadG(0);
    int r = lane >> 2, c2 = (lane & 3) * 2;
    for (int it = 0; it < NIT; it++) {
        stS();
        __syncthreads();
        if (it + 1 < NIT) loadG(it + 1);

        uint32_t afr[2][4], bfr[8][2];
        #pragma unroll
        for (int mi = 0; mi < 2; mi++) {
            int row = wm * 32 + mi * 16 + r;
            afr[mi][0] = *(const uint32_t*)&As[row][c2];
            afr[mi][1] = *(const uint32_t*)&As[row + 8][c2];
            afr[mi][2] = *(const uint32_t*)&As[row][c2 + 8];
            afr[mi][3] = *(const uint32_t*)&As[row + 8][c2 + 8];
        }
        #pragma unroll
        for (int ni = 0; ni < 8; ni++) {
            int col = wn * 64 + ni * 8 + r;
            bfr[ni][0] = *(const uint32_t*)&Bs[col][c2];
            bfr[ni][1] = *(const uint32_t*)&Bs[col][c2 + 8];
        }
        #pragma unroll
        for (int mi = 0; mi < 2; mi++)
            #pragma unroll
            for (int ni = 0; ni < 8; ni++)
                mma16816(acc[mi][ni], afr[mi], bfr[ni]);
        __syncthreads();
    }

    #pragma unroll
    for (int mi = 0; mi < 2; mi++)
        #pragma unroll
        for (int hh = 0; hh < 2; hh++) {
            int row = m0 + wm * 32 + mi * 16 + r + hh * 8;
            if (row < NN) {
                #pragma unroll
                for (int ni = 0; ni < 8; ni++) {
                    int col = wn * 64 + ni * 8 + c2;
                    if (MODE == 0) {
                        *(__half2*)(g_Wh16 + (size_t)row * 1024 + sl * 128 + col) =
                            __float22half2_rn(make_float2(acc[mi][ni][hh * 2], acc[mi][ni][hh * 2 + 1]));
                    } else {
                        *(float2*)(g_Wh2part + (size_t)sl * NN * HIDD + (size_t)row * HIDD + col) =
                            make_float2(acc[mi][ni][hh * 2], acc[mi][ni][hh * 2 + 1]);
                    }
                }
            }
        }
}

// ---------------- f1/f2 (transposed [h][n] layout) ----------------
__global__ __launch_bounds__(128) void f12_kernel(const float* __restrict__ a_heads) {
    int gw   = blockIdx.x * 4 + (threadIdx.x >> 5);   // gw = n*8 + h
    int lane = threadIdx.x & 31;
    if (gw >= NN * NH) return;
    int h = gw & 7, n = gw >> 3;
    const __half2* wh = (const __half2*)(g_Wh16 + (size_t)gw * HIDD);
    const float* a1 = a_heads + h * 2 * HIDD;
    float s1 = 0.f, s2 = 0.f;
    #pragma unroll
    for (int i = 0; i < 2; i++) {
        int o2 = lane + i * 32;
        float2 w = __half22float2(wh[o2]);
        s1 += w.x * a1[2 * o2] + w.y * a1[2 * o2 + 1];
        s2 += w.x * a1[HIDD + 2 * o2] + w.y * a1[HIDD + 2 * o2 + 1];
    }
    #pragma unroll
    for (int off = 16; off; off >>= 1) {
        s1 += __shfl_down_sync(0xffffffffu, s1, off);
        s2 += __shfl_down_sync(0xffffffffu, s2, off);
    }
    if (lane == 0) { g_f1c[h * NN + n] = s1; g_f2c[h * NN + n] = s2; }
}

// ---------------- wedge: exact row max + w=exp(v-max) + 1/rowsum ----------------
// L=0: grid (NTIL, 8); L=1: grid (NTIL, 1)
template <int L>
__global__ __launch_bounds__(1024) void wedge_kernel() {
    int h = blockIdx.y;
    int wid = threadIdx.x >> 5, lane = threadIdx.x & 31;
    int row = blockIdx.x * 32 + wid;
    if (row >= NN) return;      // no block syncs below
    int beg = g_rowptr[row], end = g_rowptr[row + 1];
    float f1n = (L == 0) ? g_f1c[h * NN + row] : g_g1[row];
    const float* __restrict__ f2p = (L == 0) ? (g_f2c + h * NN) : g_g2;

    float m = -3.0e38f;
    for (int j = beg + lane; j < end; j += 32) {
        float v = f1n + f2p[g_cols[j]];
        v = (v > 0.f) ? v : ALPHAK * v;
        m = fmaxf(m, v);
    }
    #pragma unroll
    for (int o = 16; o; o >>= 1) m = fmaxf(m, __shfl_xor_sync(0xffffffffu, m, o));

    float s = 0.f;
    uint2* __restrict__ cw = g_cw + (size_t)h * EMAX;
    for (int j = beg + lane; j < end; j += 32) {
        int col = g_cols[j];
        float v = f1n + f2p[col];
        v = (v > 0.f) ? v : ALPHAK * v;
        float w = __expf(v - m);
        s += w;
        cw[j] = make_uint2(__float_as_uint(w), (unsigned)col);
    }
    #pragma unroll
    for (int o = 16; o; o >>= 1) s += __shfl_xor_sync(0xffffffffu, s, o);
    if (lane == 0) {
        if (L == 0) g_sinv1[h * NN + row] = 1.f / s;
        else        g_sinv2[row] = 1.f / s;
    }
}

// ---------------- tiled sparse aggregation: 32 rows/block, windowed for L1 reuse ----
// L=0: grid (NTIL, 8) -> g_hcat16 (ELU).  L=1: grid (NTIL, 1) -> dout fp32.
template <int L>
__global__ __launch_bounds__(1024, 1) void attn_tile(float* __restrict__ dout) {
    int h = blockIdx.y;
    int wid = threadIdx.x >> 5, lane = threadIdx.x & 31;
    int row = blockIdx.x * 32 + wid;
    bool valid = row < NN;
    int rb = (valid ? row : 0) * (NWIN + 1);
    const __half* __restrict__ Wg = (L == 0) ? (g_Wh16 + h * 128) : g_Wh2h;
    constexpr size_t wstr = (L == 0) ? 1024 : 128;
    const uint2* __restrict__ cw = g_cw + (size_t)h * EMAX;
    const __half* Wl = Wg + lane * 4;

    float a0 = 0.f, a1 = 0.f, a2 = 0.f, a3 = 0.f;

    for (int win = 0; win < NWIN; win++) {
        int j0 = valid ? g_rpw[rb + win]     : 0;
        int j1 = valid ? g_rpw[rb + win + 1] : 0;
        int j = j0;
        for (; j + 1 < j1; j += 2) {
            uint2 c0 = __ldg(&cw[j]);
            uint2 c1 = __ldg(&cw[j + 1]);
            uint2 d0 = *(const uint2*)(Wl + (size_t)c0.y * wstr);
            uint2 d1 = *(const uint2*)(Wl + (size_t)c1.y * wstr);
            float w0 = __uint_as_float(c0.x);
            float w1 = __uint_as_float(c1.x);
            float2 p0 = __half22float2(*(__half2*)&d0.x);
            float2 p1 = __half22float2(*(__half2*)&d0.y);
            float2 q0 = __half22float2(*(__half2*)&d1.x);
            float2 q1 = __half22float2(*(__half2*)&d1.y);
            a0 = fmaf(w0, p0.x, a0); a1 = fmaf(w0, p0.y, a1);
            a2 = fmaf(w0, p1.x, a2); a3 = fmaf(w0, p1.y, a3);
            a0 = fmaf(w1, q0.x, a0); a1 = fmaf(w1, q0.y, a1);
            a2 = fmaf(w1, q1.x, a2); a3 = fmaf(w1, q1.y, a3);
        }
        if (j < j1) {
            uint2 c0 = __ldg(&cw[j]);
            uint2 d0 = *(const uint2*)(Wl + (size_t)c0.y * wstr);
            float w0 = __uint_as_float(c0.x);
            float2 p0 = __half22float2(*(__half2*)&d0.x);
            float2 p1 = __half22float2(*(__half2*)&d0.y);
            a0 = fmaf(w0, p0.x, a0); a1 = fmaf(w0, p0.y, a1);
            a2 = fmaf(w0, p1.x, a2); a3 = fmaf(w0, p1.y, a3);
        }
        __syncthreads();
    }

    if (valid) {
        if (L == 0) {
            float inv = g_sinv1[h * NN + row];
            a0 *= inv; a1 *= inv; a2 *= inv; a3 *= inv;
            a0 = (a0 > 0.f) ? a0 : expm1f(a0);
            a1 = (a1 > 0.f) ? a1 : expm1f(a1);
            a2 = (a2 > 0.f) ? a2 : expm1f(a2);
            a3 = (a3 > 0.f) ? a3 : expm1f(a3);
            __half2 h0 = __float22half2_rn(make_float2(a0, a1));
            __half2 h1 = __float22half2_rn(make_float2(a2, a3));
            uint2 o2;
            o2.x = *reinterpret_cast<uint32_t*>(&h0);
            o2.y = *reinterpret_cast<uint32_t*>(&h1);
            *(uint2*)(g_hcat16 + (size_t)row * 1024 + h * 128 + lane * 4) = o2;
        } else {
            float inv = g_sinv2[row];
            *(float4*)(dout + (size_t)row * HIDD + lane * 4) =
                make_float4(a0 * inv, a1 * inv, a2 * inv, a3 * inv);
        }
    }
}

// ---------------- split-K reduce + g1/g2 + fp16 Wh2 ----------------
__global__ __launch_bounds__(128) void reduce_g12_kernel(const float* __restrict__ a_out) {
    int n = blockIdx.x, t = threadIdx.x;
    size_t idx = (size_t)n * HIDD + t;
    float w = g_Wh2part[idx]
            + g_Wh2part[(size_t)NN * HIDD + idx]
            + g_Wh2part[(size_t)2 * NN * HIDD + idx]
            + g_Wh2part[(size_t)3 * NN * HIDD + idx];
    g_Wh2h[idx] = __float2half_rn(w);
    __shared__ float r1[128], r2[128];
    r1[t] = w * a_out[t];
    r2[t] = w * a_out[HIDD + t];
    __syncthreads();
    for (int o = 64; o; o >>= 1) {
        if (t < o) { r1[t] += r1[t + o]; r2[t] += r2[t + o]; }
        __syncthreads();
    }
    if (t == 0) { g_g1[n] = r1[0]; g_g2[n] = r2[0]; }
}

// ---------------- launch ----------------
extern "C" void kernel_launch(void* const* d_in, const int* in_sizes, int n_in,
                              void* d_out, int out_size) {
    const float* x       = (const float*)d_in[0];
    const float* adj     = (const float*)d_in[1];
    const float* W_heads = (const float*)d_in[2];
    const float* a_heads = (const float*)d_in[3];
    const float* W_out   = (const float*)d_in[4];
    const float* a_out   = (const float*)d_in[5];
    float* out = (float*)d_out;

    count_kernel<<<1500, 128>>>(adj);
    scan_kernel<<<1, 1024>>>();
    fill_kernel<<<1500, 128>>>();
    rpw_kernel<<<NN, 64>>>();
    x16_kernel<<<(NN * 304 + 255) / 256, 256>>>(x);

    hgemm<0><<<dim3(47, 8), 256>>>(W_heads);
    f12_kernel<<<(NN * NH + 3) / 4, 128>>>(a_heads);

    wedge_kernel<0><<<dim3(NTIL, NH), 1024>>>();
    attn_tile<0><<<dim3(NTIL, NH), 1024>>>(out);

    hgemm<1><<<dim3(47, 4), 256>>>(W_out);
    reduce_g12_kernel<<<NN, 128>>>(a_out);

    wedge_kernel<1><<<dim3(NTIL, 1), 1024>>>();
    attn_tile<1><<<dim3(NTIL, 1), 1024>>>(out);
}

// round 6
// speedup vs baseline: 1.5376x; 1.2858x over previous
#include <cuda_runtime.h>
#include <cuda_fp16.h>
#include <cstdint>

#define NN    6000
#define FIN   300
#define HIDD  128
#define NH    8
#define ALPHAK 0.2f
#define EMAX  2200000
#define SCAN_CH 6          // ceil(6000/1024)
#define NW 188             // ceil(6000/32)

// ---------------- device scratch ----------------
__device__ __align__(256) __half g_Wh16[NN * NH * HIDD];   // [n][h][c]
__device__ __align__(256) __half g_x16[NN * 304];          // fp16 x, K padded
__device__ float    g_f1c[NH * NN];                        // [h][n]
__device__ float    g_f2c[NH * NN];                        // [h][n]
__device__ unsigned g_f2maxU[NH];
__device__ __align__(256) __half g_hcat16[NN * NH * HIDD];
__device__ float    g_Wh2part[4 * NN * HIDD];
__device__ __align__(256) __half g_Wh2h[NN * HIDD];
__device__ float    g_g1[NN];
__device__ float    g_g2[NN];
__device__ unsigned g_g2maxU[1];
__device__ int      g_rowptr[NN + 1];
__device__ unsigned g_bits[NN * NW];
__device__ int      g_cols[EMAX];

// ordered-int float max encoding
__device__ __forceinline__ unsigned encf(float f) {
    int b = __float_as_int(f);
    return (b >= 0) ? ((unsigned)b | 0x80000000u) : (unsigned)(~b);
}
__device__ __forceinline__ float decf(unsigned k) {
    int b = (k & 0x80000000u) ? (int)(k & 0x7fffffffu) : ~(int)k;
    return __int_as_float(b);
}

// ---------------- CSR build ----------------
__global__ __launch_bounds__(128) void count_kernel(const float* __restrict__ adj) {
    int row  = blockIdx.x * 4 + (threadIdx.x >> 5);
    int lane = threadIdx.x & 31;
    if (row >= NN) return;
    const float* arow = adj + (size_t)row * NN;
    int cnt = 0;
    for (int w0 = 0; w0 < NW; w0++) {
        int col = w0 * 32 + lane;
        float v = (col < NN) ? arow[col] : 0.f;
        unsigned b = __ballot_sync(0xffffffffu, v > 0.f);
        if (lane == 0) {
            g_bits[row * NW + w0] = b;
            cnt += __popc(b);
        }
    }
    if (lane == 0) g_rowptr[row + 1] = cnt;
}

__global__ __launch_bounds__(1024) void scan_kernel() {
    __shared__ int part[1024];
    int t = threadIdx.x;
    if (t < NH) g_f2maxU[t] = 0u;
    if (t == NH) g_g2maxU[0] = 0u;
    int base = t * SCAN_CH;
    int loc[SCAN_CH];
    int s = 0;
    #pragma unroll
    for (int i = 0; i < SCAN_CH; i++) {
        int idx = base + i;
        int v = (idx < NN) ? g_rowptr[idx + 1] : 0;
        s += v;
        loc[i] = s;
    }
    part[t] = s;
    __syncthreads();
    for (int off = 1; off < 1024; off <<= 1) {
        int v = 0;
        if (t >= off) v = part[t - off];
        __syncthreads();
        if (t >= off) part[t] += v;
        __syncthreads();
    }
    int excl = (t == 0) ? 0 : part[t - 1];
    #pragma unroll
    for (int i = 0; i < SCAN_CH; i++) {
        int idx = base + i;
        if (idx < NN) g_rowptr[idx + 1] = excl + loc[i];
    }
    if (t == 0) g_rowptr[0] = 0;
}

__global__ __launch_bounds__(128) void fill_kernel() {
    int row  = blockIdx.x * 4 + (threadIdx.x >> 5);
    int lane = threadIdx.x & 31;
    if (row >= NN) return;
    int base = g_rowptr[row];
    for (int w0 = 0; w0 < NW; w0++) {
        unsigned bits = g_bits[row * NW + w0];
        if (bits) {
            if ((bits >> lane) & 1u) {
                int pos = base + __popc(bits & ((1u << lane) - 1u));
                g_cols[pos] = w0 * 32 + lane;
            }
            base += __popc(bits);
        }
    }
}

// ---------------- x -> fp16 padded ----------------
__global__ __launch_bounds__(256) void x16_kernel(const float* __restrict__ x) {
    int i = blockIdx.x * 256 + threadIdx.x;
    if (i >= NN * 304) return;
    int n = i / 304, c = i - n * 304;
    g_x16[i] = (c < FIN) ? __float2half_rn(x[(size_t)n * FIN + c]) : __ushort_as_half(0);
}

// ---------------- tensor-core fp16 GEMM, double-buffered ----------------
__device__ __forceinline__ void mma16816(float* c, const uint32_t* a, const uint32_t* b) {
    asm volatile(
        "mma.sync.aligned.m16n8k16.row.col.f32.f16.f16.f32 "
        "{%0,%1,%2,%3}, {%4,%5,%6,%7}, {%8,%9}, {%0,%1,%2,%3};\n"
        : "+f"(c[0]), "+f"(c[1]), "+f"(c[2]), "+f"(c[3])
        : "r"(a[0]), "r"(a[1]), "r"(a[2]), "r"(a[3]), "r"(b[0]), "r"(b[1]));
}

// MODE 0: g_Wh16[m][h*128+c] = x16 @ W_heads[h], grid (47, 8)
// MODE 1: g_Wh2part[s] = hcat16[:, s*256:(s+1)*256] @ W_out[s*256:,:], grid (47, 4)
template <int MODE>
__global__ __launch_bounds__(256) void hgemm(const float* __restrict__ Bf) {
    constexpr int NIT  = (MODE == 0) ? 19 : 16;   // K = 304 / 256
    constexpr int KVAL = (MODE == 0) ? FIN : 256;
    __shared__ __half As[2][128][18];
    __shared__ __half Bs[2][128][18];

    int tid  = threadIdx.x;
    int lane = tid & 31;
    int wid  = tid >> 5;
    int wm = wid & 3, wn = wid >> 2;
    int m0 = blockIdx.x * 128;
    int sl = blockIdx.y;
    const float*  Bg = Bf + (size_t)sl * ((MODE == 0) ? FIN * HIDD : 256 * HIDD);
    const __half* Ag = (MODE == 0) ? g_x16 : (g_hcat16 + sl * 256);
    const int lda = (MODE == 0) ? 304 : 1024;

    float acc[2][8][4];
    #pragma unroll
    for (int i = 0; i < 2; i++)
        #pragma unroll
        for (int j = 0; j < 8; j++)
            #pragma unroll
            for (int q = 0; q < 4; q++) acc[i][j][q] = 0.f;

    uint4  ph;
    float4 pb0, pb1;
    const float4 Z4 = make_float4(0.f, 0.f, 0.f, 0.f);

    int ar = tid >> 1, ahoff = (tid & 1) * 8;
    int bkr = tid >> 4, bc0 = (tid & 15) * 8;

    auto loadG = [&](int it) {
        int k0 = it * 16;
        int gr = m0 + ar;
        ph = (gr < NN) ? *(const uint4*)(Ag + (size_t)gr * lda + k0 + ahoff)
                       : make_uint4(0u, 0u, 0u, 0u);
        bool kok = (k0 + bkr) < KVAL;
        pb0 = kok ? *(const float4*)(Bg + (size_t)(k0 + bkr) * HIDD + bc0)     : Z4;
        pb1 = kok ? *(const float4*)(Bg + (size_t)(k0 + bkr) * HIDD + bc0 + 4) : Z4;
    };

    auto stS = [&](int buf) {
        *(uint32_t*)&As[buf][ar][ahoff]     = ph.x;
        *(uint32_t*)&As[buf][ar][ahoff + 2] = ph.y;
        *(uint32_t*)&As[buf][ar][ahoff + 4] = ph.z;
        *(uint32_t*)&As[buf][ar][ahoff + 6] = ph.w;
        Bs[buf][bc0 + 0][bkr] = __float2half_rn(pb0.x);
        Bs[buf][bc0 + 1][bkr] = __float2half_rn(pb0.y);
        Bs[buf][bc0 + 2][bkr] = __float2half_rn(pb0.z);
        Bs[buf][bc0 + 3][bkr] = __float2half_rn(pb0.w);
        Bs[buf][bc0 + 4][bkr] = __float2half_rn(pb1.x);
        Bs[buf][bc0 + 5][bkr] = __float2half_rn(pb1.y);
        Bs[buf][bc0 + 6][bkr] = __float2half_rn(pb1.z);
        Bs[buf][bc0 + 7][bkr] = __float2half_rn(pb1.w);
    };

    loadG(0);
    stS(0);
    __syncthreads();

    int r = lane >> 2, c2 = (lane & 3) * 2;
    for (int it = 0; it < NIT; it++) {
        int cur = it & 1;
        if (it + 1 < NIT) loadG(it + 1);

        uint32_t afr[2][4], bfr[8][2];
        #pragma unroll
        for (int mi = 0; mi < 2; mi++) {
            int row = wm * 32 + mi * 16 + r;
            afr[mi][0] = *(const uint32_t*)&As[cur][row][c2];
            afr[mi][1] = *(const uint32_t*)&As[cur][row + 8][c2];
            afr[mi][2] = *(const uint32_t*)&As[cur][row][c2 + 8];
            afr[mi][3] = *(const uint32_t*)&As[cur][row + 8][c2 + 8];
        }
        #pragma unroll
        for (int ni = 0; ni < 8; ni++) {
            int col = wn * 64 + ni * 8 + r;
            bfr[ni][0] = *(const uint32_t*)&Bs[cur][col][c2];
            bfr[ni][1] = *(const uint32_t*)&Bs[cur][col][c2 + 8];
        }
        #pragma unroll
        for (int mi = 0; mi < 2; mi++)
            #pragma unroll
            for (int ni = 0; ni < 8; ni++)
                mma16816(acc[mi][ni], afr[mi], bfr[ni]);

        if (it + 1 < NIT) stS(cur ^ 1);
        __syncthreads();
    }

    #pragma unroll
    for (int mi = 0; mi < 2; mi++)
        #pragma unroll
        for (int hh = 0; hh < 2; hh++) {
            int row = m0 + wm * 32 + mi * 16 + r + hh * 8;
            if (row < NN) {
                #pragma unroll
                for (int ni = 0; ni < 8; ni++) {
                    int col = wn * 64 + ni * 8 + c2;
                    if (MODE == 0) {
                        *(__half2*)(g_Wh16 + (size_t)row * 1024 + sl * 128 + col) =
                            __float22half2_rn(make_float2(acc[mi][ni][hh * 2], acc[mi][ni][hh * 2 + 1]));
                    } else {
                        *(float2*)(g_Wh2part + (size_t)sl * NN * HIDD + (size_t)row * HIDD + col) =
                            make_float2(acc[mi][ni][hh * 2], acc[mi][ni][hh * 2 + 1]);
                    }
                }
            }
        }
}

// ---------------- f1/f2 ([h][n] layout) + fused f2max atomic ----------------
__global__ __launch_bounds__(128) void f12_kernel(const float* __restrict__ a_heads) {
    int gw   = blockIdx.x * 4 + (threadIdx.x >> 5);   // gw = n*8 + h
    int lane = threadIdx.x & 31;
    if (gw >= NN * NH) return;
    int h = gw & 7, n = gw >> 3;
    const __half2* wh = (const __half2*)(g_Wh16 + (size_t)gw * HIDD);
    const float* a1 = a_heads + h * 2 * HIDD;
    float s1 = 0.f, s2 = 0.f;
    #pragma unroll
    for (int i = 0; i < 2; i++) {
        int o2 = lane + i * 32;
        float2 w = __half22float2(wh[o2]);
        s1 += w.x * a1[2 * o2] + w.y * a1[2 * o2 + 1];
        s2 += w.x * a1[HIDD + 2 * o2] + w.y * a1[HIDD + 2 * o2 + 1];
    }
    #pragma unroll
    for (int off = 16; off; off >>= 1) {
        s1 += __shfl_down_sync(0xffffffffu, s1, off);
        s2 += __shfl_down_sync(0xffffffffu, s2, off);
    }
    if (lane == 0) {
        g_f1c[h * NN + n] = s1;
        g_f2c[h * NN + n] = s2;
        atomicMax(&g_f2maxU[h], encf(s2));
    }
}

// ---------------- layer-1: warp-per-(node,head), 32 nodes/block, no syncs ----------
__global__ __launch_bounds__(1024) void attn1_kernel() {
    int h = blockIdx.y;
    int w = threadIdx.x >> 5, lane = threadIdx.x & 31;
    int row = blockIdx.x * 32 + w;
    if (row >= NN) return;
    float f1n   = g_f1c[h * NN + row];
    float shift = f1n + decf(g_f2maxU[h]);
    const float* __restrict__ f2p = g_f2c + h * NN;
    int beg = g_rowptr[row], end = g_rowptr[row + 1];
    const __half* Wl = g_Wh16 + h * 128 + lane * 4;

    float a0 = 0.f, a1 = 0.f, a2 = 0.f, a3 = 0.f, s = 0.f;

    for (int j0 = beg; j0 < end; j0 += 32) {
        int j = j0 + lane;
        int col = 0; float wgt = 0.f;
        if (j < end) {
            col = g_cols[j];
            float v = f1n + f2p[col];
            v = (v > 0.f) ? v : ALPHAK * v;
            wgt = __expf(v - shift);
            s += wgt;
        }
        int lim = min(32, end - j0);
        #pragma unroll 4
        for (int e = 0; e < lim; e++) {
            float we = __shfl_sync(0xffffffffu, wgt, e);
            int   ce = __shfl_sync(0xffffffffu, col, e);
            uint2 d = *(const uint2*)(Wl + (size_t)ce * 1024);
            float2 p0 = __half22float2(*(__half2*)&d.x);
            float2 p1 = __half22float2(*(__half2*)&d.y);
            a0 = fmaf(we, p0.x, a0); a1 = fmaf(we, p0.y, a1);
            a2 = fmaf(we, p1.x, a2); a3 = fmaf(we, p1.y, a3);
        }
    }
    #pragma unroll
    for (int o = 16; o; o >>= 1) s += __shfl_xor_sync(0xffffffffu, s, o);
    float inv = 1.f / s;
    a0 *= inv; a1 *= inv; a2 *= inv; a3 *= inv;
    a0 = (a0 > 0.f) ? a0 : expm1f(a0);
    a1 = (a1 > 0.f) ? a1 : expm1f(a1);
    a2 = (a2 > 0.f) ? a2 : expm1f(a2);
    a3 = (a3 > 0.f) ? a3 : expm1f(a3);
    __half2 h0 = __float22half2_rn(make_float2(a0, a1));
    __half2 h1 = __float22half2_rn(make_float2(a2, a3));
    uint2 o2;
    o2.x = *reinterpret_cast<uint32_t*>(&h0);
    o2.y = *reinterpret_cast<uint32_t*>(&h1);
    *(uint2*)(g_hcat16 + (size_t)row * 1024 + h * 128 + lane * 4) = o2;
}

// ---------------- split-K reduce + g1/g2 (+g2max atomic) + fp16 Wh2 ----------------
__global__ __launch_bounds__(128) void reduce_g12_kernel(const float* __restrict__ a_out) {
    int n = blockIdx.x, t = threadIdx.x;
    size_t idx = (size_t)n * HIDD + t;
    float w = g_Wh2part[idx]
            + g_Wh2part[(size_t)NN * HIDD + idx]
            + g_Wh2part[(size_t)2 * NN * HIDD + idx]
            + g_Wh2part[(size_t)3 * NN * HIDD + idx];
    g_Wh2h[idx] = __float2half_rn(w);
    __shared__ float r1[128], r2[128];
    r1[t] = w * a_out[t];
    r2[t] = w * a_out[HIDD + t];
    __syncthreads();
    for (int o = 64; o; o >>= 1) {
        if (t < o) { r1[t] += r1[t + o]; r2[t] += r2[t + o]; }
        __syncthreads();
    }
    if (t == 0) {
        g_g1[n] = r1[0];
        g_g2[n] = r2[0];
        atomicMax(&g_g2maxU[0], encf(r2[0]));
    }
}

// ---------------- layer-2: warp-per-node, 8 nodes/block ----------------
__global__ __launch_bounds__(256) void attn2_kernel(float* __restrict__ dout) {
    int w = threadIdx.x >> 5, lane = threadIdx.x & 31;
    int row = blockIdx.x * 8 + w;
    if (row >= NN) return;
    float g1n   = g_g1[row];
    float shift = g1n + decf(g_g2maxU[0]);
    int beg = g_rowptr[row], end = g_rowptr[row + 1];
    const __half* Wl = g_Wh2h + lane * 4;

    float a0 = 0.f, a1 = 0.f, a2 = 0.f, a3 = 0.f, s = 0.f;

    for (int j0 = beg; j0 < end; j0 += 32) {
        int j = j0 + lane;
        int col = 0; float wgt = 0.f;
        if (j < end) {
            col = g_cols[j];
            float v = g1n + g_g2[col];
            v = (v > 0.f) ? v : ALPHAK * v;
            wgt = __expf(v - shift);
            s += wgt;
        }
        int lim = min(32, end - j0);
        #pragma unroll 4
        for (int e = 0; e < lim; e++) {
            float we = __shfl_sync(0xffffffffu, wgt, e);
            int   ce = __shfl_sync(0xffffffffu, col, e);
            uint2 d = *(const uint2*)(Wl + (size_t)ce * 128);
            float2 p0 = __half22float2(*(__half2*)&d.x);
            float2 p1 = __half22float2(*(__half2*)&d.y);
            a0 = fmaf(we, p0.x, a0); a1 = fmaf(we, p0.y, a1);
            a2 = fmaf(we, p1.x, a2); a3 = fmaf(we, p1.y, a3);
        }
    }
    #pragma unroll
    for (int o = 16; o; o >>= 1) s += __shfl_xor_sync(0xffffffffu, s, o);
    float inv = 1.f / s;
    *(float4*)(dout + (size_t)row * HIDD + lane * 4) =
        make_float4(a0 * inv, a1 * inv, a2 * inv, a3 * inv);
}

// ---------------- launch ----------------
extern "C" void kernel_launch(void* const* d_in, const int* in_sizes, int n_in,
                              void* d_out, int out_size) {
    const float* x       = (const float*)d_in[0];
    const float* adj     = (const float*)d_in[1];
    const float* W_heads = (const float*)d_in[2];
    const float* a_heads = (const float*)d_in[3];
    const float* W_out   = (const float*)d_in[4];
    const float* a_out   = (const float*)d_in[5];
    float* out = (float*)d_out;

    count_kernel<<<1500, 128>>>(adj);
    scan_kernel<<<1, 1024>>>();
    fill_kernel<<<1500, 128>>>();
    x16_kernel<<<(NN * 304 + 255) / 256, 256>>>(x);

    hgemm<0><<<dim3(47, 8), 256>>>(W_heads);
    f12_kernel<<<(NN * NH + 3) / 4, 128>>>(a_heads);

    attn1_kernel<<<dim3(188, NH), 1024>>>();

    hgemm<1><<<dim3(47, 4), 256>>>(W_out);
    reduce_g12_kernel<<<NN, 128>>>(a_out);

    attn2_kernel<<<750, 256>>>(out);
}

// round 7
// speedup vs baseline: 1.6658x; 1.0834x over previous
#include <cuda_runtime.h>
#include <cuda_fp16.h>
#include <cstdint>

#define NN    6000
#define FIN   300
#define HIDD  128
#define NH    8
#define ALPHAK 0.2f
#define EMAX  2200000
#define SCAN_CH 6          // ceil(6000/1024)
#define NW 188             // ceil(6000/32)

// ---------------- device scratch ----------------
__device__ __align__(256) __half g_Wh16[NN * NH * HIDD];   // [n][h][c]
__device__ __align__(256) __half g_x16[NN * 304];          // fp16 x, K padded
__device__ float    g_f1c[NH * NN];                        // [h][n]
__device__ float    g_f2c[NH * NN];                        // [h][n]
__device__ unsigned g_f2maxU[NH];
__device__ __align__(256) __half g_hcat16[NN * NH * HIDD];
__device__ float    g_Wh2part[4 * NN * HIDD];
__device__ __align__(256) __half g_Wh2h[NN * HIDD];
__device__ float    g_g1[NN];
__device__ float    g_g2[NN];
__device__ unsigned g_g2maxU[1];
__device__ int      g_rowptr[NN + 1];
__device__ unsigned g_bits[NN * NW];
__device__ int      g_cols[EMAX];

// ordered-int float max encoding
__device__ __forceinline__ unsigned encf(float f) {
    int b = __float_as_int(f);
    return (b >= 0) ? ((unsigned)b | 0x80000000u) : (unsigned)(~b);
}
__device__ __forceinline__ float decf(unsigned k) {
    int b = (k & 0x80000000u) ? (int)(k & 0x7fffffffu) : ~(int)k;
    return __int_as_float(b);
}

// ---------------- CSR build (side stream) ----------------
__global__ __launch_bounds__(128) void count_kernel(const float* __restrict__ adj) {
    int row  = blockIdx.x * 4 + (threadIdx.x >> 5);
    int lane = threadIdx.x & 31;
    if (row >= NN) return;
    const float* arow = adj + (size_t)row * NN;
    int cnt = 0;
    for (int w0 = 0; w0 < NW; w0++) {
        int col = w0 * 32 + lane;
        float v = (col < NN) ? arow[col] : 0.f;
        unsigned b = __ballot_sync(0xffffffffu, v > 0.f);
        if (lane == 0) {
            g_bits[row * NW + w0] = b;
            cnt += __popc(b);
        }
    }
    if (lane == 0) g_rowptr[row + 1] = cnt;
}

__global__ __launch_bounds__(1024) void scan_kernel() {
    __shared__ int part[1024];
    int t = threadIdx.x;
    int base = t * SCAN_CH;
    int loc[SCAN_CH];
    int s = 0;
    #pragma unroll
    for (int i = 0; i < SCAN_CH; i++) {
        int idx = base + i;
        int v = (idx < NN) ? g_rowptr[idx + 1] : 0;
        s += v;
        loc[i] = s;
    }
    part[t] = s;
    __syncthreads();
    for (int off = 1; off < 1024; off <<= 1) {
        int v = 0;
        if (t >= off) v = part[t - off];
        __syncthreads();
        if (t >= off) part[t] += v;
        __syncthreads();
    }
    int excl = (t == 0) ? 0 : part[t - 1];
    #pragma unroll
    for (int i = 0; i < SCAN_CH; i++) {
        int idx = base + i;
        if (idx < NN) g_rowptr[idx + 1] = excl + loc[i];
    }
    if (t == 0) g_rowptr[0] = 0;
}

__global__ __launch_bounds__(128) void fill_kernel() {
    int row  = blockIdx.x * 4 + (threadIdx.x >> 5);
    int lane = threadIdx.x & 31;
    if (row >= NN) return;
    int base = g_rowptr[row];
    for (int w0 = 0; w0 < NW; w0++) {
        unsigned bits = g_bits[row * NW + w0];
        if (bits) {
            if ((bits >> lane) & 1u) {
                int pos = base + __popc(bits & ((1u << lane) - 1u));
                g_cols[pos] = w0 * 32 + lane;
            }
            base += __popc(bits);
        }
    }
}

// ---------------- x -> fp16 padded (+ zero the max atomics) ----------------
__global__ __launch_bounds__(256) void x16_kernel(const float* __restrict__ x) {
    if (blockIdx.x == 0) {
        if (threadIdx.x < NH) g_f2maxU[threadIdx.x] = 0u;
        if (threadIdx.x == NH) g_g2maxU[0] = 0u;
    }
    int i = blockIdx.x * 256 + threadIdx.x;
    if (i >= NN * 304) return;
    int n = i / 304, c = i - n * 304;
    g_x16[i] = (c < FIN) ? __float2half_rn(x[(size_t)n * FIN + c]) : __ushort_as_half(0);
}

// ---------------- tensor-core fp16 GEMM, double-buffered ----------------
__device__ __forceinline__ void mma16816(float* c, const uint32_t* a, const uint32_t* b) {
    asm volatile(
        "mma.sync.aligned.m16n8k16.row.col.f32.f16.f16.f32 "
        "{%0,%1,%2,%3}, {%4,%5,%6,%7}, {%8,%9}, {%0,%1,%2,%3};\n"
        : "+f"(c[0]), "+f"(c[1]), "+f"(c[2]), "+f"(c[3])
        : "r"(a[0]), "r"(a[1]), "r"(a[2]), "r"(a[3]), "r"(b[0]), "r"(b[1]));
}

// MODE 0: g_Wh16 = x16 @ W_heads[h]; epilogue also computes f1/f2 rows. grid (47, 8)
// MODE 1: g_Wh2part[s] = hcat16[:, s*256:(s+1)*256] @ W_out[s*256:,:]. grid (47, 4)
template <int MODE>
__global__ __launch_bounds__(256) void hgemm(const float* __restrict__ Bf,
                                             const float* __restrict__ a_heads) {
    constexpr int NIT  = (MODE == 0) ? 19 : 16;   // K = 304 / 256
    constexpr int KVAL = (MODE == 0) ? FIN : 256;
    __shared__ __half As[2][128][18];
    __shared__ __half Bs[2][128][18];
    __shared__ float s1sh[128], s2sh[128];

    int tid  = threadIdx.x;
    int lane = tid & 31;
    int wid  = tid >> 5;
    int wm = wid & 3, wn = wid >> 2;
    int m0 = blockIdx.x * 128;
    int sl = blockIdx.y;
    const float*  Bg = Bf + (size_t)sl * ((MODE == 0) ? FIN * HIDD : 256 * HIDD);
    const __half* Ag = (MODE == 0) ? g_x16 : (g_hcat16 + sl * 256);
    const int lda = (MODE == 0) ? 304 : 1024;

    if (MODE == 0 && tid < 128) { s1sh[tid] = 0.f; s2sh[tid] = 0.f; }

    float acc[2][8][4];
    #pragma unroll
    for (int i = 0; i < 2; i++)
        #pragma unroll
        for (int j = 0; j < 8; j++)
            #pragma unroll
            for (int q = 0; q < 4; q++) acc[i][j][q] = 0.f;

    uint4  ph;
    float4 pb0, pb1;
    const float4 Z4 = make_float4(0.f, 0.f, 0.f, 0.f);

    int ar = tid >> 1, ahoff = (tid & 1) * 8;
    int bkr = tid >> 4, bc0 = (tid & 15) * 8;

    auto loadG = [&](int it) {
        int k0 = it * 16;
        int gr = m0 + ar;
        ph = (gr < NN) ? *(const uint4*)(Ag + (size_t)gr * lda + k0 + ahoff)
                       : make_uint4(0u, 0u, 0u, 0u);
        bool kok = (k0 + bkr) < KVAL;
        pb0 = kok ? *(const float4*)(Bg + (size_t)(k0 + bkr) * HIDD + bc0)     : Z4;
        pb1 = kok ? *(const float4*)(Bg + (size_t)(k0 + bkr) * HIDD + bc0 + 4) : Z4;
    };

    auto stS = [&](int buf) {
        *(uint32_t*)&As[buf][ar][ahoff]     = ph.x;
        *(uint32_t*)&As[buf][ar][ahoff + 2] = ph.y;
        *(uint32_t*)&As[buf][ar][ahoff + 4] = ph.z;
        *(uint32_t*)&As[buf][ar][ahoff + 6] = ph.w;
        Bs[buf][bc0 + 0][bkr] = __float2half_rn(pb0.x);
        Bs[buf][bc0 + 1][bkr] = __float2half_rn(pb0.y);
        Bs[buf][bc0 + 2][bkr] = __float2half_rn(pb0.z);
        Bs[buf][bc0 + 3][bkr] = __float2half_rn(pb0.w);
        Bs[buf][bc0 + 4][bkr] = __float2half_rn(pb1.x);
        Bs[buf][bc0 + 5][bkr] = __float2half_rn(pb1.y);
        Bs[buf][bc0 + 6][bkr] = __float2half_rn(pb1.z);
        Bs[buf][bc0 + 7][bkr] = __float2half_rn(pb1.w);
    };

    loadG(0);
    stS(0);
    __syncthreads();

    int r = lane >> 2, c2 = (lane & 3) * 2;
    for (int it = 0; it < NIT; it++) {
        int cur = it & 1;
        if (it + 1 < NIT) loadG(it + 1);

        uint32_t afr[2][4], bfr[8][2];
        #pragma unroll
        for (int mi = 0; mi < 2; mi++) {
            int row = wm * 32 + mi * 16 + r;
            afr[mi][0] = *(const uint32_t*)&As[cur][row][c2];
            afr[mi][1] = *(const uint32_t*)&As[cur][row + 8][c2];
            afr[mi][2] = *(const uint32_t*)&As[cur][row][c2 + 8];
            afr[mi][3] = *(const uint32_t*)&As[cur][row + 8][c2 + 8];
        }
        #pragma unroll
        for (int ni = 0; ni < 8; ni++) {
            int col = wn * 64 + ni * 8 + r;
            bfr[ni][0] = *(const uint32_t*)&Bs[cur][col][c2];
            bfr[ni][1] = *(const uint32_t*)&Bs[cur][col][c2 + 8];
        }
        #pragma unroll
        for (int mi = 0; mi < 2; mi++)
            #pragma unroll
            for (int ni = 0; ni < 8; ni++)
                mma16816(acc[mi][ni], afr[mi], bfr[ni]);

        if (it + 1 < NIT) stS(cur ^ 1);
        __syncthreads();
    }

    // store C
    #pragma unroll
    for (int mi = 0; mi < 2; mi++)
        #pragma unroll
        for (int hh = 0; hh < 2; hh++) {
            int row = m0 + wm * 32 + mi * 16 + r + hh * 8;
            if (row < NN) {
                #pragma unroll
                for (int ni = 0; ni < 8; ni++) {
                    int col = wn * 64 + ni * 8 + c2;
                    if (MODE == 0) {
                        *(__half2*)(g_Wh16 + (size_t)row * 1024 + sl * 128 + col) =
                            __float22half2_rn(make_float2(acc[mi][ni][hh * 2], acc[mi][ni][hh * 2 + 1]));
                    } else {
                        *(float2*)(g_Wh2part + (size_t)sl * NN * HIDD + (size_t)row * HIDD + col) =
                            make_float2(acc[mi][ni][hh * 2], acc[mi][ni][hh * 2 + 1]);
                    }
                }
            }
        }

    // fused f1/f2 epilogue (MODE 0)
    if (MODE == 0) {
        const float* a1 = a_heads + sl * 2 * HIDD;
        float p1[2][2] = {{0.f, 0.f}, {0.f, 0.f}};
        float p2[2][2] = {{0.f, 0.f}, {0.f, 0.f}};
        #pragma unroll
        for (int ni = 0; ni < 8; ni++) {
            int colb = wn * 64 + ni * 8 + c2;
            float a1x = a1[colb],        a1y = a1[colb + 1];
            float a2x = a1[HIDD + colb], a2y = a1[HIDD + colb + 1];
            #pragma unroll
            for (int mi = 0; mi < 2; mi++)
                #pragma unroll
                for (int hh = 0; hh < 2; hh++) {
                    p1[mi][hh] += acc[mi][ni][hh * 2] * a1x + acc[mi][ni][hh * 2 + 1] * a1y;
                    p2[mi][hh] += acc[mi][ni][hh * 2] * a2x + acc[mi][ni][hh * 2 + 1] * a2y;
                }
        }
        // reduce over the 4 lanes sharing a row (lane bits 0..1)
        #pragma unroll
        for (int off = 1; off <= 2; off <<= 1)
            #pragma unroll
            for (int mi = 0; mi < 2; mi++)
                #pragma unroll
                for (int hh = 0; hh < 2; hh++) {
                    p1[mi][hh] += __shfl_xor_sync(0xffffffffu, p1[mi][hh], off);
                    p2[mi][hh] += __shfl_xor_sync(0xffffffffu, p2[mi][hh], off);
                }
        if ((lane & 3) == 0) {
            #pragma unroll
            for (int mi = 0; mi < 2; mi++)
                #pragma unroll
                for (int hh = 0; hh < 2; hh++) {
                    int rl = wm * 32 + mi * 16 + r + hh * 8;
                    atomicAdd(&s1sh[rl], p1[mi][hh]);
                    atomicAdd(&s2sh[rl], p2[mi][hh]);
                }
        }
        __syncthreads();
        if (tid < 128) {
            int row = m0 + tid;
            if (row < NN) {
                g_f1c[sl * NN + row] = s1sh[tid];
                g_f2c[sl * NN + row] = s2sh[tid];
                atomicMax(&g_f2maxU[sl], encf(s2sh[tid]));
            }
        }
    }
}

// ---------------- layer-1: warp-per-(node,head), 2-edge unrolled gather ----------
__global__ __launch_bounds__(1024) void attn1_kernel() {
    int h = blockIdx.y;
    int w = threadIdx.x >> 5, lane = threadIdx.x & 31;
    int row = blockIdx.x * 32 + w;
    if (row >= NN) return;
    float f1n   = g_f1c[h * NN + row];
    float shift = f1n + decf(g_f2maxU[h]);
    const float* __restrict__ f2p = g_f2c + h * NN;
    int beg = g_rowptr[row], end = g_rowptr[row + 1];
    const __half* Wl = g_Wh16 + h * 128 + lane * 4;

    float a0 = 0.f, a1 = 0.f, a2 = 0.f, a3 = 0.f, s = 0.f;

    for (int j0 = beg; j0 < end; j0 += 32) {
        int j = j0 + lane;
        int col = 0; float wgt = 0.f;
        if (j < end) {
            col = g_cols[j];
            float v = f1n + f2p[col];
            v = (v > 0.f) ? v : ALPHAK * v;
            wgt = __expf(v - shift);
            s += wgt;
        }
        int lim = min(32, end - j0);
        int e = 0;
        for (; e + 1 < lim; e += 2) {
            float w0 = __shfl_sync(0xffffffffu, wgt, e);
            float w1 = __shfl_sync(0xffffffffu, wgt, e + 1);
            int   c0 = __shfl_sync(0xffffffffu, col, e);
            int   c1 = __shfl_sync(0xffffffffu, col, e + 1);
            uint2 d0 = __ldg((const uint2*)(Wl + (size_t)c0 * 1024));
            uint2 d1 = __ldg((const uint2*)(Wl + (size_t)c1 * 1024));
            float2 p0 = __half22float2(*(__half2*)&d0.x);
            float2 p1 = __half22float2(*(__half2*)&d0.y);
            float2 q0 = __half22float2(*(__half2*)&d1.x);
            float2 q1 = __half22float2(*(__half2*)&d1.y);
            a0 = fmaf(w0, p0.x, a0); a1 = fmaf(w0, p0.y, a1);
            a2 = fmaf(w0, p1.x, a2); a3 = fmaf(w0, p1.y, a3);
            a0 = fmaf(w1, q0.x, a0); a1 = fmaf(w1, q0.y, a1);
            a2 = fmaf(w1, q1.x, a2); a3 = fmaf(w1, q1.y, a3);
        }
        if (e < lim) {
            float w0 = __shfl_sync(0xffffffffu, wgt, e);
            int   c0 = __shfl_sync(0xffffffffu, col, e);
            uint2 d0 = __ldg((const uint2*)(Wl + (size_t)c0 * 1024));
            float2 p0 = __half22float2(*(__half2*)&d0.x);
            float2 p1 = __half22float2(*(__half2*)&d0.y);
            a0 = fmaf(w0, p0.x, a0); a1 = fmaf(w0, p0.y, a1);
            a2 = fmaf(w0, p1.x, a2); a3 = fmaf(w0, p1.y, a3);
        }
    }
    #pragma unroll
    for (int o = 16; o; o >>= 1) s += __shfl_xor_sync(0xffffffffu, s, o);
    float inv = 1.f / s;
    a0 *= inv; a1 *= inv; a2 *= inv; a3 *= inv;
    a0 = (a0 > 0.f) ? a0 : expm1f(a0);
    a1 = (a1 > 0.f) ? a1 : expm1f(a1);
    a2 = (a2 > 0.f) ? a2 : expm1f(a2);
    a3 = (a3 > 0.f) ? a3 : expm1f(a3);
    __half2 h0 = __float22half2_rn(make_float2(a0, a1));
    __half2 h1 = __float22half2_rn(make_float2(a2, a3));
    uint2 o2;
    o2.x = *reinterpret_cast<uint32_t*>(&h0);
    o2.y = *reinterpret_cast<uint32_t*>(&h1);
    *(uint2*)(g_hcat16 + (size_t)row * 1024 + h * 128 + lane * 4) = o2;
}

// ---------------- split-K reduce + g1/g2 (+g2max) + fp16 Wh2 ----------------
__global__ __launch_bounds__(128) void reduce_g12_kernel(const float* __restrict__ a_out) {
    int n = blockIdx.x, t = threadIdx.x;
    size_t idx = (size_t)n * HIDD + t;
    float w = g_Wh2part[idx]
            + g_Wh2part[(size_t)NN * HIDD + idx]
            + g_Wh2part[(size_t)2 * NN * HIDD + idx]
            + g_Wh2part[(size_t)3 * NN * HIDD + idx];
    g_Wh2h[idx] = __float2half_rn(w);
    __shared__ float r1[128], r2[128];
    r1[t] = w * a_out[t];
    r2[t] = w * a_out[HIDD + t];
    __syncthreads();
    for (int o = 64; o; o >>= 1) {
        if (t < o) { r1[t] += r1[t + o]; r2[t] += r2[t + o]; }
        __syncthreads();
    }
    if (t == 0) {
        g_g1[n] = r1[0];
        g_g2[n] = r2[0];
        atomicMax(&g_g2maxU[0], encf(r2[0]));
    }
}

// ---------------- layer-2: warp-per-node, 2-edge unrolled ----------------
__global__ __launch_bounds__(256) void attn2_kernel(float* __restrict__ dout) {
    int w = threadIdx.x >> 5, lane = threadIdx.x & 31;
    int row = blockIdx.x * 8 + w;
    if (row >= NN) return;
    float g1n   = g_g1[row];
    float shift = g1n + decf(g_g2maxU[0]);
    int beg = g_rowptr[row], end = g_rowptr[row + 1];
    const __half* Wl = g_Wh2h + lane * 4;

    float a0 = 0.f, a1 = 0.f, a2 = 0.f, a3 = 0.f, s = 0.f;

    for (int j0 = beg; j0 < end; j0 += 32) {
        int j = j0 + lane;
        int col = 0; float wgt = 0.f;
        if (j < end) {
            col = g_cols[j];
            float v = g1n + g_g2[col];
            v = (v > 0.f) ? v : ALPHAK * v;
            wgt = __expf(v - shift);
            s += wgt;
        }
        int lim = min(32, end - j0);
        int e = 0;
        for (; e + 1 < lim; e += 2) {
            float w0 = __shfl_sync(0xffffffffu, wgt, e);
            float w1 = __shfl_sync(0xffffffffu, wgt, e + 1);
            int   c0 = __shfl_sync(0xffffffffu, col, e);
            int   c1 = __shfl_sync(0xffffffffu, col, e + 1);
            uint2 d0 = __ldg((const uint2*)(Wl + (size_t)c0 * 128));
            uint2 d1 = __ldg((const uint2*)(Wl + (size_t)c1 * 128));
            float2 p0 = __half22float2(*(__half2*)&d0.x);
            float2 p1 = __half22float2(*(__half2*)&d0.y);
            float2 q0 = __half22float2(*(__half2*)&d1.x);
            float2 q1 = __half22float2(*(__half2*)&d1.y);
            a0 = fmaf(w0, p0.x, a0); a1 = fmaf(w0, p0.y, a1);
            a2 = fmaf(w0, p1.x, a2); a3 = fmaf(w0, p1.y, a3);
            a0 = fmaf(w1, q0.x, a0); a1 = fmaf(w1, q0.y, a1);
            a2 = fmaf(w1, q1.x, a2); a3 = fmaf(w1, q1.y, a3);
        }
        if (e < lim) {
            float w0 = __shfl_sync(0xffffffffu, wgt, e);
            int   c0 = __shfl_sync(0xffffffffu, col, e);
            uint2 d0 = __ldg((const uint2*)(Wl + (size_t)c0 * 128));
            float2 p0 = __half22float2(*(__half2*)&d0.x);
            float2 p1 = __half22float2(*(__half2*)&d0.y);
            a0 = fmaf(w0, p0.x, a0); a1 = fmaf(w0, p0.y, a1);
            a2 = fmaf(w0, p1.x, a2); a3 = fmaf(w0, p1.y, a3);
        }
    }
    #pragma unroll
    for (int o = 16; o; o >>= 1) s += __shfl_xor_sync(0xffffffffu, s, o);
    float inv = 1.f / s;
    *(float4*)(dout + (size_t)row * HIDD + lane * 4) =
        make_float4(a0 * inv, a1 * inv, a2 * inv, a3 * inv);
}

// ---------------- launch ----------------
extern "C" void kernel_launch(void* const* d_in, const int* in_sizes, int n_in,
                              void* d_out, int out_size) {
    const float* x       = (const float*)d_in[0];
    const float* adj     = (const float*)d_in[1];
    const float* W_heads = (const float*)d_in[2];
    const float* a_heads = (const float*)d_in[3];
    const float* W_out   = (const float*)d_in[4];
    const float* a_out   = (const float*)d_in[5];
    float* out = (float*)d_out;

    // one-time stream/event setup (first call is the non-captured correctness run)
    static cudaStream_t s_csr = nullptr;
    static cudaEvent_t evFork = nullptr, evCSR = nullptr;
    if (s_csr == nullptr) {
        cudaStreamCreateWithFlags(&s_csr, cudaStreamNonBlocking);
        cudaEventCreateWithFlags(&evFork, cudaEventDisableTiming);
        cudaEventCreateWithFlags(&evCSR, cudaEventDisableTiming);
    }

    // fork: CSR build on side stream
    cudaEventRecord(evFork, 0);
    cudaStreamWaitEvent(s_csr, evFork, 0);
    count_kernel<<<1500, 128, 0, s_csr>>>(adj);
    scan_kernel<<<1, 1024, 0, s_csr>>>();
    fill_kernel<<<1500, 128, 0, s_csr>>>();
    cudaEventRecord(evCSR, s_csr);

    // main stream: dense phase (independent of CSR)
    x16_kernel<<<(NN * 304 + 255) / 256, 256>>>(x);
    hgemm<0><<<dim3(47, 8), 256>>>(W_heads, a_heads);

    // join, then sparse phase
    cudaStreamWaitEvent(0, evCSR, 0);
    attn1_kernel<<<dim3(188, NH), 1024>>>();

    hgemm<1><<<dim3(47, 4), 256>>>(W_out, nullptr);
    reduce_g12_kernel<<<NN, 128>>>(a_out);

    attn2_kernel<<<750, 256>>>(out);
}